// round 16
// baseline (speedup 1.0000x reference)
#include <cuda_runtime.h>
#include <cuda_fp16.h>
#include <mma.h>
#include <cstdint>
#include <math.h>

using namespace nvcuda;

#define H       1024
#define DIN     512
#define T_STEPS 512
#define BATCH   32
#define DT_C    0.1f

#define GRID_R  128
#define BLOCK_R 768
#define NW      24     // warps per rec CTA
#define HB      8      // H / GRID_R

typedef unsigned long long u64;

__device__ __forceinline__ float tanh_fast(float x) {
    float e = __expf(2.0f * x);
    return 1.0f - __fdividef(2.0f, e + 1.0f);
}
__device__ __forceinline__ float sigmoid_fast(float x) {
    return __fdividef(1.0f, 1.0f + __expf(-x));
}

// ---------------- device scratch (static, allocation-free) ----------------
__device__ float g_Wr[H * H];
__device__ float g_Wi[H * H];
__device__ float g_Ux[T_STEPS * BATCH * H];
__device__ __half g_ZRh[T_STEPS * BATCH * H];        // fp16 zr history (out-GEMM A)
__device__ __half g_xh[T_STEPS * BATCH * DIN];       // fp16 x_seq
__device__ __half g_Uwh[H * DIN];                    // fp16 U_w
__device__ __half g_owh[H * H];                      // fp16 out_w
__device__ __half g_acth[2 * 3 * H * BATCH];         // fp16 act planes [buf][mat][k][b]
__device__ unsigned g_bar_count;
__device__ unsigned g_bar_gen;

// ---------------- grid-wide barrier (all CTAs resident) ----------------
__device__ __forceinline__ void grid_barrier() {
    __syncthreads();
    if (threadIdx.x == 0) {
        unsigned gen = *(volatile unsigned*)&g_bar_gen;
        __threadfence();
        unsigned t = atomicAdd(&g_bar_count, 1u);
        if (t == GRID_R - 1) {
            g_bar_count = 0u;
            __threadfence();
            atomicAdd(&g_bar_gen, 1u);
        } else {
            while (*(volatile unsigned*)&g_bar_gen == gen) { }
        }
        __threadfence();
    }
    __syncthreads();
}

// ---------------- prep kernels ----------------
__global__ void prep_kernel(const float* __restrict__ Wr_w, const float* __restrict__ mask_r,
                            const float* __restrict__ Wi_w, const float* __restrict__ mask_i) {
    int i = blockIdx.x * blockDim.x + threadIdx.x;
    if (i < H * H) {
        g_Wr[i] = Wr_w[i] * (1.0f / (1.0f + expf(-mask_r[i])));
        g_Wi[i] = Wi_w[i] * (1.0f / (1.0f + expf(-mask_i[i])));
    }
}

__global__ void init_kernel() {
    int i = blockIdx.x * blockDim.x + threadIdx.x;
    if (i < 2 * 3 * H * BATCH) g_acth[i] = __float2half(0.0f);
}

__global__ void cvt_half_kernel(const float* __restrict__ s, __half* __restrict__ d, int n) {
    int i = blockIdx.x * blockDim.x + threadIdx.x;
    if (i < n) d[i] = __float2half(s[i]);
}

// ---------------- fp16 HMMA GEMM (wmma): C[MxN] = A[MxK] @ B[NxK]^T + bias ----------------
#define WG_TM 128
#define WG_TN 64
#define WG_TK 32
#define WG_PAD 8

__global__ __launch_bounds__(256) void hgemm_wmma(
    const __half* __restrict__ A, const __half* __restrict__ Bm,
    const float* __restrict__ bias, float* __restrict__ C,
    int M, int N, int K) {
    __shared__ __half As[WG_TM][WG_TK + WG_PAD];
    __shared__ __half Bs[WG_TN][WG_TK + WG_PAD];
    __shared__ float  Cs[WG_TM][WG_TN];

    const int tid = threadIdx.x;
    const int wid = tid >> 5;
    const int bm = blockIdx.y * WG_TM;
    const int bn = blockIdx.x * WG_TN;
    const int wr = wid >> 1;
    const int wc = wid & 1;

    wmma::fragment<wmma::accumulator, 16, 16, 16, float> acc[2][2];
#pragma unroll
    for (int i = 0; i < 2; i++)
#pragma unroll
        for (int j = 0; j < 2; j++) wmma::fill_fragment(acc[i][j], 0.0f);

    for (int k0 = 0; k0 < K; k0 += WG_TK) {
#pragma unroll
        for (int i = tid; i < WG_TM * WG_TK / 8; i += 256) {
            int r = i >> 2;
            int c = (i & 3) * 8;
            *(uint4*)&As[r][c] = *(const uint4*)(A + (size_t)(bm + r) * K + k0 + c);
        }
#pragma unroll
        for (int i = tid; i < WG_TN * WG_TK / 8; i += 256) {
            int r = i >> 2;
            int c = (i & 3) * 8;
            *(uint4*)&Bs[r][c] = *(const uint4*)(Bm + (size_t)(bn + r) * K + k0 + c);
        }
        __syncthreads();

#pragma unroll
        for (int kk = 0; kk < WG_TK; kk += 16) {
            wmma::fragment<wmma::matrix_a, 16, 16, 16, __half, wmma::row_major> af[2];
            wmma::fragment<wmma::matrix_b, 16, 16, 16, __half, wmma::col_major> bf[2];
#pragma unroll
            for (int i = 0; i < 2; i++)
                wmma::load_matrix_sync(af[i], &As[wr * 32 + i * 16][kk], WG_TK + WG_PAD);
#pragma unroll
            for (int j = 0; j < 2; j++)
                wmma::load_matrix_sync(bf[j], &Bs[wc * 32 + j * 16][kk], WG_TK + WG_PAD);
#pragma unroll
            for (int i = 0; i < 2; i++)
#pragma unroll
                for (int j = 0; j < 2; j++)
                    wmma::mma_sync(acc[i][j], af[i], bf[j], acc[i][j]);
        }
        __syncthreads();
    }

#pragma unroll
    for (int i = 0; i < 2; i++)
#pragma unroll
        for (int j = 0; j < 2; j++)
            wmma::store_matrix_sync(&Cs[wr * 32 + i * 16][wc * 32 + j * 16],
                                    acc[i][j], WG_TN, wmma::mem_row_major);
    __syncthreads();

#pragma unroll
    for (int i = tid; i < WG_TM * WG_TN / 4; i += 256) {
        int r = i >> 4;
        int c = (i & 15) * 4;
        float4 v = *(float4*)&Cs[r][c];
        float4 b4 = *(const float4*)(bias + bn + c);
        v.x += b4.x; v.y += b4.y; v.z += b4.z; v.w += b4.w;
        *(float4*)&C[(size_t)(bm + r) * N + bn + c] = v;
    }
}

// ---------------- persistent recurrence kernel: HMMA mainloop ----------------
// 24 warps: warp w -> (mat m = w/8, k-slice g = w%8 covering k in [g*128,(g+1)*128)).
// Per warp/step: 8 k-steps of wmma 16x16x16 (2 batch-frags), act chunks double-buffered
// through warp-private SMEM. k-slices reduced via red[] by the 256 update threads.
struct RecSmem {
    __half Wh[3][H][16];            // fp16 weights, rows padded 8->16 (96KB)
    __half astage[NW][2][16 * 32];  // per-warp act chunk double buffer (48KB)
    float  red[NW][2][256];         // acc frags [warp][bfrag][16x16 row-major] (48KB)
    __half acth[3][HB][BATCH];      // staged fp16 act planes
    float  wb[3][HB];
    float  br[HB], bi[HB], tb[HB];
};

__global__ void __launch_bounds__(BLOCK_R, 1) rec_kernel(
    const float* __restrict__ Wt_w,
    const float* __restrict__ Wr_b, const float* __restrict__ Wi_b,
    const float* __restrict__ Wt_b, const float* __restrict__ b_real,
    const float* __restrict__ b_imag, const float* __restrict__ tau_bias) {
    extern __shared__ char smem_raw[];
    RecSmem& sm = *reinterpret_cast<RecSmem*>(smem_raw);
    const int tid = threadIdx.x;
    const int hbase = blockIdx.x * HB;

    // ---- load fp16 weights into SMEM [mat][k][16] (cols 8..15 zero) ----
    for (int idx = tid; idx < 3 * H * 16; idx += BLOCK_R) {
        int m   = idx >> 14;           // /(H*16)
        int rem = idx & 16383;
        int k   = rem >> 4;
        int c   = rem & 15;
        float w = 0.0f;
        if (c < 8) {
            long ri = (long)(hbase + c) * H + k;
            w = (m == 0) ? g_Wr[ri] : (m == 1) ? g_Wi[ri] : Wt_w[ri];
        }
        sm.Wh[m][k][c] = __float2half(w);
    }
    if (tid < HB) {
        sm.wb[0][tid] = Wr_b[hbase + tid];
        sm.wb[1][tid] = Wi_b[hbase + tid];
        sm.wb[2][tid] = Wt_b[hbase + tid];
        sm.br[tid] = b_real[hbase + tid];
        sm.bi[tid] = b_imag[hbase + tid];
        sm.tb[tid] = tau_bias[hbase + tid];
    }
    __syncthreads();

    const int w    = tid >> 5;        // warp 0..23
    const int lane = tid & 31;
    const int m    = w >> 3;          // mat 0..2
    const int g    = w & 7;           // k-slice 0..7
    const int krow = lane >> 1;       // staging row (k within chunk)
    const int bh   = (lane & 1) * 16; // staging batch-half offset

    __half* st0 = &sm.astage[w][0][0];
    __half* st1 = &sm.astage[w][1][0];

    // update-thread mapping
    const int cb  = tid >> 3;
    const int chl = tid & 7;
    const int mf  = cb >> 4;                    // batch fragment 0/1
    const int rix = (cb & 15) * 16 + chl;       // index in red frag
    float zr = 0.0f, zi = 0.0f;

    int cur = 0;
    for (int t = 0; t < T_STEPS; t++) {
        float ux = 0.0f;
        if (tid < HB * BATCH)
            ux = __ldg(&g_Ux[((long)t * BATCH + cb) * H + hbase + chl]);

        // ---- HMMA mainloop ----
        const __half* planep = g_acth + (size_t)(cur * 3 + m) * (H * BATCH);
        const __half* srcbase = planep + ((size_t)g * 128 + krow) * BATCH + bh;

        wmma::fragment<wmma::accumulator, 16, 16, 16, float> acc0, acc1;
        wmma::fill_fragment(acc0, 0.0f);
        wmma::fill_fragment(acc1, 0.0f);

        // stage chunk 0
        {
            const uint4* s = (const uint4*)srcbase;
            uint4* d = (uint4*)(st0 + krow * 32 + bh);
            d[0] = s[0];
            d[1] = s[1];
        }
        __syncwarp();

        int buf = 0;
#pragma unroll
        for (int c = 0; c < 8; c++) {
            uint4 v0, v1;
            if (c < 7) {
                const uint4* s = (const uint4*)(srcbase + (size_t)(c + 1) * 16 * BATCH);
                v0 = s[0];
                v1 = s[1];
            }
            __half* bufp = buf ? st1 : st0;
            int kabs = g * 128 + c * 16;
            wmma::fragment<wmma::matrix_a, 16, 16, 16, __half, wmma::col_major> af0, af1;
            wmma::fragment<wmma::matrix_b, 16, 16, 16, __half, wmma::row_major> bf;
            wmma::load_matrix_sync(af0, bufp, 32);
            wmma::load_matrix_sync(af1, bufp + 16, 32);
            wmma::load_matrix_sync(bf, &sm.Wh[m][kabs][0], 16);
            wmma::mma_sync(acc0, af0, bf, acc0);
            wmma::mma_sync(acc1, af1, bf, acc1);
            if (c < 7) {
                __half* obuf = buf ? st0 : st1;
                uint4* d = (uint4*)(obuf + krow * 32 + bh);
                d[0] = v0;
                d[1] = v1;
                __syncwarp();
            }
            buf ^= 1;
        }
        wmma::store_matrix_sync(&sm.red[w][0][0], acc0, 16, wmma::mem_row_major);
        wmma::store_matrix_sync(&sm.red[w][1][0], acc1, 16, wmma::mem_row_major);
        __syncthreads();

        // ---- update: reduce 8 k-slices, elementwise, stage fp16 acts ----
        if (tid < HB * BATCH) {
            float s0 = 0.0f, s1 = 0.0f, s2 = 0.0f;
#pragma unroll
            for (int g2 = 0; g2 < 8; g2++) {
                s0 += sm.red[0 * 8 + g2][mf][rix];
                s1 += sm.red[1 * 8 + g2][mf][rix];
                s2 += sm.red[2 * 8 + g2][mf][rix];
            }
            int b  = cb;
            int hl = chl;
            int h  = hbase + hl;
            float wr = s0 + sm.wb[0][hl];
            float wi = s1 + sm.wb[1][hl];
            float wt = s2 + sm.wb[2][hl];
            float dr = -zr + wr + ux + sm.br[hl];
            float di = -zi + wi + ux + sm.bi[hl];
            float tau = sigmoid_fast(wt) + sm.tb[hl];
            tau = fminf(fmaxf(tau, 0.01f), 1.0f) + 1e-6f;
            float rtau = __fdividef(1.0f, tau);
            dr = fminf(fmaxf(dr * rtau, -10.0f), 10.0f);
            di = fminf(fmaxf(di * rtau, -10.0f), 10.0f);
            zr = fminf(fmaxf(zr + DT_C * dr, -100.0f), 100.0f);
            zi = fminf(fmaxf(zi + DT_C * di, -100.0f), 100.0f);
            g_ZRh[((long)t * BATCH + b) * H + h] = __float2half(zr);
            sm.acth[0][hl][b] = __float2half(tanh_fast(zr));
            sm.acth[1][hl][b] = __float2half(tanh_fast(zi));
            sm.acth[2][hl][b] = __float2half(sqrtf(zr * zr + zi * zi));
        }
        __syncthreads();

        // coalesced store of the 3 fp16 act planes (96 x 16B)
        const int nxt = cur ^ 1;
        if (tid < 96) {
            int p  = tid >> 5;
            int of = (tid & 31) * 16;  // bytes
            uint4 v = *(const uint4*)((const char*)&sm.acth[p][0][0] + of);
            *(uint4*)((char*)(g_acth + ((size_t)(nxt * 3 + p) * H + hbase) * BATCH) + of) = v;
        }

        grid_barrier();
        cur ^= 1;
    }
}

// ---------------- launch ----------------
extern "C" void kernel_launch(void* const* d_in, const int* in_sizes, int n_in,
                              void* d_out, int out_size) {
    const float* x_seq    = (const float*)d_in[0];
    const float* Wr_w     = (const float*)d_in[1];
    const float* Wr_b     = (const float*)d_in[2];
    const float* Wi_w     = (const float*)d_in[3];
    const float* Wi_b     = (const float*)d_in[4];
    const float* U_w      = (const float*)d_in[5];
    const float* U_b      = (const float*)d_in[6];
    const float* Wt_w     = (const float*)d_in[7];
    const float* Wt_b     = (const float*)d_in[8];
    const float* b_real   = (const float*)d_in[9];
    const float* b_imag   = (const float*)d_in[10];
    const float* mask_r   = (const float*)d_in[11];
    const float* mask_i   = (const float*)d_in[12];
    const float* tau_bias = (const float*)d_in[13];
    const float* out_w    = (const float*)d_in[14];
    const float* out_b    = (const float*)d_in[15];
    float* y = (float*)d_out;

    float* p_Ux = nullptr;
    __half *p_xh = nullptr, *p_Uwh = nullptr, *p_owh = nullptr, *p_ZRh = nullptr;
    cudaGetSymbolAddress((void**)&p_Ux, g_Ux);
    cudaGetSymbolAddress((void**)&p_xh, g_xh);
    cudaGetSymbolAddress((void**)&p_Uwh, g_Uwh);
    cudaGetSymbolAddress((void**)&p_owh, g_owh);
    cudaGetSymbolAddress((void**)&p_ZRh, g_ZRh);

    prep_kernel<<<(H * H + 255) / 256, 256>>>(Wr_w, mask_r, Wi_w, mask_i);
    init_kernel<<<(2 * 3 * H * BATCH + 255) / 256, 256>>>();

    cvt_half_kernel<<<(T_STEPS * BATCH * DIN + 255) / 256, 256>>>(x_seq, p_xh, T_STEPS * BATCH * DIN);
    cvt_half_kernel<<<(H * DIN + 255) / 256, 256>>>(U_w, p_Uwh, H * DIN);
    cvt_half_kernel<<<(H * H + 255) / 256, 256>>>(out_w, p_owh, H * H);

    // Ux = x @ U_w^T + U_b  (HMMA)
    {
        dim3 grid(H / WG_TN, (T_STEPS * BATCH) / WG_TM);
        hgemm_wmma<<<grid, 256>>>(p_xh, p_Uwh, U_b, p_Ux, T_STEPS * BATCH, H, DIN);
    }

    // persistent recurrence (HMMA mainloop)
    {
        int smem = (int)sizeof(RecSmem);
        cudaFuncSetAttribute(rec_kernel, cudaFuncAttributeMaxDynamicSharedMemorySize, smem);
        rec_kernel<<<GRID_R, BLOCK_R, smem>>>(Wt_w, Wr_b, Wi_b, Wt_b, b_real, b_imag, tau_bias);
    }

    // y = ZR @ out_w^T + out_b  (HMMA)
    {
        dim3 grid(H / WG_TN, (T_STEPS * BATCH) / WG_TM);
        hgemm_wmma<<<grid, 256>>>(p_ZRh, p_owh, out_b, y, T_STEPS * BATCH, H, H);
    }
}